// round 7
// baseline (speedup 1.0000x reference)
#include <cuda_runtime.h>

// RelationAwareAttention: B=1, H=8, L=512, D=64
// out = concat(attn_sum[1,8,512,64], p_attn[1,8,512,512]) as float32.

#define L_SEQ 512
#define D_DIM 64
#define H_HEADS 8
#define NTHREADS 256

__global__ __launch_bounds__(NTHREADS, 6)
void rel_attn_kernel(const float* __restrict__ q_g,
                     const float* __restrict__ k_g,
                     const float* __restrict__ v_g,
                     const float* __restrict__ rk_g,
                     const float* __restrict__ rv_g,
                     const int*   __restrict__ mask_g,
                     float* __restrict__ out_attn,
                     float* __restrict__ out_p)
{
    const int i    = blockIdx.x;   // query position
    const int h    = blockIdx.y;   // head
    const int tid  = threadIdx.x;
    const int warp = tid >> 5;
    const int lane = tid & 31;

    __shared__ float  s_score[L_SEQ];
    __shared__ int    s_mask[L_SEQ];
    __shared__ float  s_red[8];
    __shared__ float4 s_acc[16][16];   // [j-group][d-quad]

    const float* q    = q_g  + ((size_t)h * L_SEQ + i) * D_DIM;
    const float* krow = k_g  + (size_t)h * L_SEQ * D_DIM;
    const float* rk   = rk_g + (((size_t)h * L_SEQ + i) * L_SEQ) * D_DIM;
    const int*   mrow = mask_g + (size_t)i * L_SEQ;   // mask broadcast over h (B=1)

    // Preload mask row (coalesced) into smem.
    s_mask[tid]       = mrow[tid];
    s_mask[tid + 256] = mrow[tid + 256];
    __syncthreads();

    // ---------------- Phase 1: scores ----------------
    // score[j] = (q . (k[j] + rk[i,j])) / sqrt(64), masked.
    // Warp w owns j in [w*64, (w+1)*64). 8-lane groups: each lane holds
    // 8 d-floats, so one warp computes 4 j's per iteration with 3 shuffles.
    const int g8 = lane >> 3;   // 0..3: which j of the 4 this group owns
    const int l8 = lane & 7;    // lane within 8-lane group

    const float4 qa = *reinterpret_cast<const float4*>(q + 8 * l8);
    const float4 qb = *reinterpret_cast<const float4*>(q + 8 * l8 + 4);

    #pragma unroll 2
    for (int it = 0; it < 16; ++it) {
        const int j = (warp << 6) + (it << 2) + g8;
        const float* kj = krow + (size_t)j * D_DIM + 8 * l8;
        const float* rj = rk   + (size_t)j * D_DIM + 8 * l8;
        const float4 ka = *reinterpret_cast<const float4*>(kj);
        const float4 kb = *reinterpret_cast<const float4*>(kj + 4);
        const float4 ra = *reinterpret_cast<const float4*>(rj);
        const float4 rb = *reinterpret_cast<const float4*>(rj + 4);
        float p = qa.x * (ka.x + ra.x) + qa.y * (ka.y + ra.y)
                + qa.z * (ka.z + ra.z) + qa.w * (ka.w + ra.w)
                + qb.x * (kb.x + rb.x) + qb.y * (kb.y + rb.y)
                + qb.z * (kb.z + rb.z) + qb.w * (kb.w + rb.w);
        // reduce over the 8 lanes of this group (xor masks stay within group)
        p += __shfl_xor_sync(0xffffffffu, p, 4);
        p += __shfl_xor_sync(0xffffffffu, p, 2);
        p += __shfl_xor_sync(0xffffffffu, p, 1);
        if (l8 == 0) {
            float s = p * 0.125f;                 // 1/sqrt(64)
            if (s_mask[j] == 0) s = -1e9f;
            s_score[j] = s;
        }
    }
    __syncthreads();

    // ---------------- Phase 2: softmax over j ----------------
    // Each thread owns scores tid and tid+256.
    float v0 = s_score[tid];
    float v1 = s_score[tid + 256];

    // max-reduce
    float m = fmaxf(v0, v1);
    #pragma unroll
    for (int o = 16; o > 0; o >>= 1)
        m = fmaxf(m, __shfl_xor_sync(0xffffffffu, m, o));
    if (lane == 0) s_red[warp] = m;
    __syncthreads();
    if (tid == 0) {
        float mm = s_red[0];
        #pragma unroll
        for (int w = 1; w < 8; ++w) mm = fmaxf(mm, s_red[w]);
        s_red[0] = mm;
    }
    __syncthreads();
    m = s_red[0];
    __syncthreads();   // protect s_red before reuse

    // exp + sum-reduce
    const float e0 = __expf(v0 - m);
    const float e1 = __expf(v1 - m);
    float ssum = e0 + e1;
    #pragma unroll
    for (int o = 16; o > 0; o >>= 1)
        ssum += __shfl_xor_sync(0xffffffffu, ssum, o);
    if (lane == 0) s_red[warp] = ssum;
    __syncthreads();
    if (tid == 0) {
        float tot = s_red[0];
        #pragma unroll
        for (int w = 1; w < 8; ++w) tot += s_red[w];
        s_red[0] = tot;
    }
    __syncthreads();
    const float inv = 1.0f / s_red[0];

    const float p0 = e0 * inv;
    const float p1 = e1 * inv;
    s_score[tid]       = p0;
    s_score[tid + 256] = p1;

    // write p_attn (coalesced)
    const size_t pbase = ((size_t)h * L_SEQ + i) * L_SEQ;
    out_p[pbase + tid]       = p0;
    out_p[pbase + tid + 256] = p1;
    __syncthreads();

    // ---------------- Phase 3: output = sum_j p[j] * (v[j] + rv[i,j]) ----------------
    // 16 j-groups (warp*2 + half), each 16 lanes x float4 over d.
    const int half = lane >> 4;
    const int hl   = lane & 15;
    const int gid  = (warp << 1) + half;
    const float* vrow = v_g  + (size_t)h * L_SEQ * D_DIM;
    const float* rv   = rv_g + (((size_t)h * L_SEQ + i) * L_SEQ) * D_DIM;

    float4 acc = make_float4(0.f, 0.f, 0.f, 0.f);
    #pragma unroll 4
    for (int j = gid; j < L_SEQ; j += 16) {
        const float  pj = s_score[j];
        const float4 vv = *reinterpret_cast<const float4*>(vrow + (size_t)j * D_DIM + 4 * hl);
        const float4 rr = *reinterpret_cast<const float4*>(rv   + (size_t)j * D_DIM + 4 * hl);
        acc.x += pj * (vv.x + rr.x);
        acc.y += pj * (vv.y + rr.y);
        acc.z += pj * (vv.z + rr.z);
        acc.w += pj * (vv.w + rr.w);
    }
    s_acc[gid][hl] = acc;
    __syncthreads();

    if (tid < 16) {
        float4 r = make_float4(0.f, 0.f, 0.f, 0.f);
        #pragma unroll
        for (int gg = 0; gg < 16; ++gg) {
            const float4 a = s_acc[gg][tid];
            r.x += a.x; r.y += a.y; r.z += a.z; r.w += a.w;
        }
        float4* oa = reinterpret_cast<float4*>(out_attn + ((size_t)h * L_SEQ + i) * D_DIM);
        oa[tid] = r;
    }
}

extern "C" void kernel_launch(void* const* d_in, const int* in_sizes, int n_in,
                              void* d_out, int out_size)
{
    const float* q    = (const float*)d_in[0];
    const float* k    = (const float*)d_in[1];
    const float* v    = (const float*)d_in[2];
    const float* rk   = (const float*)d_in[3];
    const float* rv   = (const float*)d_in[4];
    const int*   mask = (const int*)  d_in[5];

    float* out      = (float*)d_out;
    float* out_attn = out;                                        // [1,8,512,64]
    float* out_p    = out + (size_t)H_HEADS * L_SEQ * D_DIM;      // [1,8,512,512]

    dim3 grid(L_SEQ, H_HEADS);
    rel_attn_kernel<<<grid, NTHREADS>>>(q, k, v, rk, rv, mask, out_attn, out_p);
}